// round 8
// baseline (speedup 1.0000x reference)
#include <cuda_runtime.h>

// x:      (4, 64, 128, 128) fp32  -> 256 independent 128x128 images
// weight: (4, 576, 128, 128) fp32 -> 9 taps per channel, tap k strided by H*W
// steps = 8
//
// ZERO-HALO cluster kernel: each 128-row image is split across a 4-CTA
// cluster (rank r owns rows 32r..32r+31). Per step, boundary rows are
// exchanged with neighbor CTAs via DSMEM remote stores into the same
// ping-pong buffer slots the halo/guard rows occupy; barrier.cluster
// (release) replaces __syncthreads. Every computed row is an output row:
// step work and weight traffic are ~2x lower than the tile+halo design.
// Inner machinery = round-5 measured optimum: 512 thr, V=2 (warp owns rows
// 2g,2g+1 in registers), packed fma.rn.f32x2 stencil, TMA cp.async.bulk
// staging for the NEXT image prefetched during the step loop (10 issuers).

#define H      128
#define W      128
#define IMG    (H * W)
#define STEPS  8
#define NIMG   256
#define NCL    32          // clusters (32x4 = 128 CTAs; <=38 same-die max)
#define SROWS  34          // row0 = top halo, 1..32 own rows, 33 = bottom halo
#define RROWS  32

#define OFF_MBAR 0
#define OFF_BUF  1024
#define OFF_WS   (OFF_BUF + 2 * SROWS * W * 4)   // 1024 + 34816  = 35840
#define OFF_XS   (OFF_WS + 9 * RROWS * W * 4)    // + 147456      = 183296
#define SMEM_TOTAL (OFF_XS + RROWS * W * 4)      // + 16384       = 199680

typedef unsigned long long u64;
typedef unsigned int u32;

__device__ __forceinline__ u32 s2u(const void* p) {
    u32 a;
    asm("{ .reg .u64 t; cvta.to.shared.u64 t, %1; cvt.u32.u64 %0, t; }"
        : "=r"(a) : "l"(p));
    return a;
}
__device__ __forceinline__ u64 pk(float lo, float hi) {
    u64 r; asm("mov.b64 %0, {%1,%2};" : "=l"(r) : "f"(lo), "f"(hi)); return r;
}
__device__ __forceinline__ void upk(u64 v, float& lo, float& hi) {
    asm("mov.b64 {%0,%1}, %2;" : "=f"(lo), "=f"(hi) : "l"(v));
}
__device__ __forceinline__ void fma2(u64& d, u64 a, u64 b) {
    asm("fma.rn.f32x2 %0, %1, %2, %0;" : "+l"(d) : "l"(a), "l"(b));
}
__device__ __forceinline__ float shup(float v) { return __shfl_up_sync(0xffffffffu, v, 1); }
__device__ __forceinline__ float shdn(float v) { return __shfl_down_sync(0xffffffffu, v, 1); }

__device__ __forceinline__ u32 ctarank() {
    u32 r; asm("mov.u32 %0, %%cluster_ctarank;" : "=r"(r)); return r;
}
__device__ __forceinline__ u32 mapa_rank(u32 addr, u32 rank) {
    u32 r;
    asm("mapa.shared::cluster.u32 %0, %1, %2;" : "=r"(r) : "r"(addr), "r"(rank));
    return r;
}
__device__ __forceinline__ void sts_remote(u32 addr, float4 v) {
    asm volatile("st.shared::cluster.v4.b32 [%0], {%1,%2,%3,%4};"
                 :: "r"(addr), "f"(v.x), "f"(v.y), "f"(v.z), "f"(v.w) : "memory");
}
#define CLUSTER_SYNC() do { \
    asm volatile("barrier.cluster.arrive.aligned;" ::: "memory"); \
    asm volatile("barrier.cluster.wait.aligned;"   ::: "memory"); \
} while (0)

__device__ __forceinline__ void mbar_wait(u32 mbar, u32 parity) {
    asm volatile(
        "{\n\t.reg .pred P;\n\t"
        "W_%=:\n\t"
        "mbarrier.try_wait.parity.shared::cta.b64 P, [%0], %1, 0x989680;\n\t"
        "@P bra.uni D_%=;\n\t"
        "bra.uni W_%=;\n\t"
        "D_%=:\n\t}"
        :: "r"(mbar), "r"(parity) : "memory");
}
__device__ __forceinline__ void bulk_g2s(u32 dst, const void* src, u32 bytes, u32 mbar) {
    asm volatile(
        "cp.async.bulk.shared::cluster.global.mbarrier::complete_tx::bytes "
        "[%0], [%1], %2, [%3];"
        :: "r"(dst), "l"(src), "r"(bytes), "r"(mbar) : "memory");
}

// Distributed prefetch of THIS CTA's 32-row slice of image `img`:
// issuer k (0..8 = weight tap k, 9 = x). mbarrier count = 10.
__device__ __forceinline__ void issue_prefetch_k(int img, int k, int rbase,
                                                 const float* x, const float* wgt,
                                                 u32 ws, u32 xs, u32 mbar) {
    const u32 bytes = RROWS * (W * 4);   // 16384
    asm volatile("mbarrier.arrive.expect_tx.shared.b64 _, [%0], %1;"
                 :: "r"(mbar), "r"(bytes) : "memory");
    if (k < 9) {
        const float* src = wgt + ((size_t)(img * 9 + k) << 14) + rbase * W;
        bulk_g2s(ws + (u32)(k * RROWS) * (W * 4), src, bytes, mbar);
    } else {
        bulk_g2s(xs, x + ((size_t)img << 14) + rbase * W, bytes, mbar);
    }
}

__global__ __launch_bounds__(512, 1) __cluster_dims__(4, 1, 1)
void diffusion_cluster_kernel(const float* __restrict__ x,
                              const float* __restrict__ wgt,
                              float* __restrict__ out)
{
    extern __shared__ char smem[];
    float (*buf)[SROWS][W] = (float (*)[SROWS][W])(smem + OFF_BUF);
    const float* wsp = (const float*)(smem + OFF_WS);
    const float* xsp = (const float*)(smem + OFF_XS);
    const u32 mbar = s2u(smem + OFF_MBAR);
    const u32 ws_a = s2u(smem + OFF_WS);
    const u32 xs_a = s2u(smem + OFF_XS);
    const u32 buf_a = s2u(smem + OFF_BUF);

    const int tid  = threadIdx.x;
    const int lane = tid & 31;
    const int warp = tid >> 5;          // 0..15; owns local rows 2g, 2g+1
    const int col0 = lane << 2;
    const int g2   = warp * 2;
    const bool issuer = (lane == 0 && warp < 10);

    const u32 rank  = ctarank();        // 0..3; owns image rows 32r..32r+31
    const int rbase = (int)rank * 32;
    const int cid   = blockIdx.x >> 2;  // cluster id 0..31

    // Remote halo targets (computed once):
    //  - my row 0  -> up neighbor's buf[b][33]   (their bottom halo)
    //  - my row 31 -> down neighbor's buf[b][0]  (their top halo)
    u32 up_dst = 0, dn_dst = 0;
    const bool send_up = (rank > 0) && (warp == 0);
    const bool send_dn = (rank < 3) && (warp == 15);
    if (send_up) up_dst = mapa_rank(buf_a, rank - 1) + (33u * W + col0) * 4u;
    if (send_dn) dn_dst = mapa_rank(buf_a, rank + 1) + (0u * W + col0) * 4u;
    const u32 bstride = (u32)(SROWS * W * 4);   // buf[1] - buf[0]

    // Guard rows at cluster edges stay zero forever (image zero padding).
    if (rank == 0 && tid < 64) {
        int b = tid >> 5;
        *(float4*)&buf[b][0][(tid & 31) << 2] = make_float4(0.f, 0.f, 0.f, 0.f);
    }
    if (rank == 3 && tid < 64) {
        int b = tid >> 5;
        *(float4*)&buf[b][SROWS - 1][(tid & 31) << 2] = make_float4(0.f, 0.f, 0.f, 0.f);
    }
    if (tid == 0) {
        asm volatile("mbarrier.init.shared.b64 [%0], 10;" :: "r"(mbar) : "memory");
    }
    __syncthreads();

    int img = cid;
    if (issuer) issue_prefetch_k(img, warp, rbase, x, wgt, ws_a, xs_a, mbar);
    u32 ph = 0;

    for (; img < NIMG; img += NCL) {
        mbar_wait(mbar, ph); ph ^= 1u;

        // ---- prologue: normalize weights into packed regs (rows all valid)
        u64 Wp[2][3][6];
        float4 y0, y1;
#pragma unroll
        for (int ro = 0; ro < 2; ro++) {
            const int rr = g2 + ro;          // local row 0..31
            float aa[9][4];
            {
                float s0 = 0.f, s1 = 0.f, s2 = 0.f, s3 = 0.f;
#pragma unroll
                for (int k = 0; k < 9; k++) {
                    float4 tv = *(const float4*)&wsp[(k * RROWS + rr) * W + col0];
                    aa[k][0] = fabsf(tv.x); aa[k][1] = fabsf(tv.y);
                    aa[k][2] = fabsf(tv.z); aa[k][3] = fabsf(tv.w);
                    s0 += aa[k][0]; s1 += aa[k][1]; s2 += aa[k][2]; s3 += aa[k][3];
                }
                const float i0 = __fdividef(1.f, s0), i1 = __fdividef(1.f, s1);
                const float i2 = __fdividef(1.f, s2), i3 = __fdividef(1.f, s3);
#pragma unroll
                for (int k = 0; k < 9; k++) {
                    aa[k][0] *= i0; aa[k][1] *= i1; aa[k][2] *= i2; aa[k][3] *= i3;
                }
                if (lane == 0)  { aa[0][0] = 0.f; aa[3][0] = 0.f; aa[6][0] = 0.f; }
                if (lane == 31) { aa[2][3] = 0.f; aa[5][3] = 0.f; aa[8][3] = 0.f; }
            }
#pragma unroll
            for (int ki = 0; ki < 3; ki++) {
                Wp[ro][ki][0] = pk(aa[ki * 3 + 0][0], aa[ki * 3 + 0][1]);
                Wp[ro][ki][1] = pk(aa[ki * 3 + 1][0], aa[ki * 3 + 1][1]);
                Wp[ro][ki][2] = pk(aa[ki * 3 + 2][0], aa[ki * 3 + 2][1]);
                Wp[ro][ki][3] = pk(aa[ki * 3 + 0][2], aa[ki * 3 + 0][3]);
                Wp[ro][ki][4] = pk(aa[ki * 3 + 1][2], aa[ki * 3 + 1][3]);
                Wp[ro][ki][5] = pk(aa[ki * 3 + 2][2], aa[ki * 3 + 2][3]);
            }
            float4 xv = *(const float4*)&xsp[rr * W + col0];
            if (ro == 0) y0 = xv; else y1 = xv;
            *(float4*)&buf[0][rr + 1][col0] = xv;
        }
        // initial x halo exchange
        if (send_up) sts_remote(up_dst, y0);            // my row 0 -> up b0
        if (send_dn) sts_remote(dn_dst, y1);            // my row 31 -> down b0
        CLUSTER_SYNC();   // staging consumed + buf[0] (incl. remote halo) visible

        // prefetch next image slice (overlaps the 8-step loop)
        if (issuer && img + NCL < NIMG)
            issue_prefetch_k(img + NCL, warp, rbase, x, wgt, ws_a, xs_a, mbar);

        // ---- 8 fused steps (round-5 body)
#pragma unroll
        for (int s = 0; s < STEPS; s++) {
            const int cb = s & 1;
            float4 va = *(const float4*)&buf[cb][g2][col0];      // row above
            float4 vb = *(const float4*)&buf[cb][g2 + 3][col0];  // row below

            const float xl0 = shup(y0.w), xr0 = shdn(y0.x);
            const float xl1 = shup(y1.w), xr1 = shdn(y1.x);
            const float xlA = shup(va.w), xrA = shdn(va.x);
            const float xlB = shup(vb.w), xrB = shdn(vb.x);

            const u64 pA0 = pk(xlA, va.x), pA1 = pk(va.x, va.y), pA2 = pk(va.y, va.z);
            const u64 pA3 = pk(va.z, va.w), pA4 = pk(va.w, xrA);
            const u64 p00 = pk(xl0, y0.x), p01 = pk(y0.x, y0.y), p02 = pk(y0.y, y0.z);
            const u64 p03 = pk(y0.z, y0.w), p04 = pk(y0.w, xr0);
            const u64 p10 = pk(xl1, y1.x), p11 = pk(y1.x, y1.y), p12 = pk(y1.y, y1.z);
            const u64 p13 = pk(y1.z, y1.w), p14 = pk(y1.w, xr1);
            const u64 pB0 = pk(xlB, vb.x), pB1 = pk(vb.x, vb.y), pB2 = pk(vb.y, vb.z);
            const u64 pB3 = pk(vb.z, vb.w), pB4 = pk(vb.w, xrB);

            u64 n001 = 0ull, n023 = 0ull, n101 = 0ull, n123 = 0ull;
            fma2(n001, Wp[0][0][0], pA0); fma2(n023, Wp[0][0][3], pA2);
            fma2(n101, Wp[1][0][0], p00); fma2(n123, Wp[1][0][3], p02);
            fma2(n001, Wp[0][0][1], pA1); fma2(n023, Wp[0][0][4], pA3);
            fma2(n101, Wp[1][0][1], p01); fma2(n123, Wp[1][0][4], p03);
            fma2(n001, Wp[0][0][2], pA2); fma2(n023, Wp[0][0][5], pA4);
            fma2(n101, Wp[1][0][2], p02); fma2(n123, Wp[1][0][5], p04);

            fma2(n001, Wp[0][1][0], p00); fma2(n023, Wp[0][1][3], p02);
            fma2(n101, Wp[1][1][0], p10); fma2(n123, Wp[1][1][3], p12);
            fma2(n001, Wp[0][1][1], p01); fma2(n023, Wp[0][1][4], p03);
            fma2(n101, Wp[1][1][1], p11); fma2(n123, Wp[1][1][4], p13);
            fma2(n001, Wp[0][1][2], p02); fma2(n023, Wp[0][1][5], p04);
            fma2(n101, Wp[1][1][2], p12); fma2(n123, Wp[1][1][5], p14);

            fma2(n001, Wp[0][2][0], p10); fma2(n023, Wp[0][2][3], p12);
            fma2(n101, Wp[1][2][0], pB0); fma2(n123, Wp[1][2][3], pB2);
            fma2(n001, Wp[0][2][1], p11); fma2(n023, Wp[0][2][4], p13);
            fma2(n101, Wp[1][2][1], pB1); fma2(n123, Wp[1][2][4], pB3);
            fma2(n001, Wp[0][2][2], p12); fma2(n023, Wp[0][2][5], p14);
            fma2(n101, Wp[1][2][2], pB2); fma2(n123, Wp[1][2][5], pB4);

            upk(n001, y0.x, y0.y); upk(n023, y0.z, y0.w);
            upk(n101, y1.x, y1.y); upk(n123, y1.z, y1.w);

            if (s < STEPS - 1) {
                const u32 nb = (u32)(cb ^ 1);
                *(float4*)&buf[nb][g2 + 1][col0] = y0;
                *(float4*)&buf[nb][g2 + 2][col0] = y1;
                if (send_up) sts_remote(up_dst + nb * bstride, y0);
                if (send_dn) sts_remote(dn_dst + nb * bstride, y1);
                CLUSTER_SYNC();   // release: local + remote publishes visible
            }
        }

        // ---- output: every computed row is exact (zero halo)
        {
            float* ob = out + (size_t)img * IMG + (rbase + g2) * W + col0;
            *(float4*)ob       = y0;
            *(float4*)(ob + W) = y1;
        }
        // Next-image prologue writes buf[0]: cluster-wide, the last reads of
        // buf[0] were at step 6, fenced by the step-6 CLUSTER_SYNC. Staging
        // reuse is fenced by the post-prologue CLUSTER_SYNC + own mbar.
    }
}

extern "C" void kernel_launch(void* const* d_in, const int* in_sizes, int n_in,
                              void* d_out, int out_size)
{
    const float* x   = (const float*)d_in[0];
    const float* wgt = (const float*)d_in[1];
    float* out       = (float*)d_out;

    cudaFuncSetAttribute(diffusion_cluster_kernel,
                         cudaFuncAttributeMaxDynamicSharedMemorySize, SMEM_TOTAL);
    // 32 clusters x 4 CTAs; 256 images = exactly 8 per cluster.
    diffusion_cluster_kernel<<<NCL * 4, 512, SMEM_TOTAL>>>(x, wgt, out);
}

// round 9
// speedup vs baseline: 1.2315x; 1.2315x over previous
#include <cuda_runtime.h>

// x:      (4, 64, 128, 128) fp32  -> 256 independent 128x128 images
// weight: (4, 576, 128, 128) fp32 -> 9 taps per channel, tap k strided by H*W
// steps = 8
//
// Round-5 architecture (measured best, 62.6us): persistent CTAs (1/SM),
// 512 thr, V=2 (warp owns region rows 2g,2g+1 in registers, vertical
// neighbors via smem ping-pong), packed fma.rn.f32x2 stencil, TMA
// cp.async.bulk staging prefetched one tile ahead (10 issuer warps).
// Round 9 deltas (latency surgery, no structural change):
//  - neighbor-row laterals read via parallel scalar LDS (clamped addresses;
//    edge correctness via zeroed edge weights) instead of LDS->SHFL serial
//  - own-row shfl+pk hoisted to before the STS/barrier of the prior step
//  - accumulator chains start with mul.rn.f32x2 (no zero-init movs) and
//    lead with own-row operands to overlap the neighbor LDS latency

#define H      128
#define W      128
#define IMG    (H * W)
#define STEPS  8
#define TH     16
#define NT     2048
#define SROWS  34
#define RROWS  32

#define OFF_MBAR 0
#define OFF_BUF  1024
#define OFF_WS   (OFF_BUF + 2 * SROWS * W * 4)   // 1024 + 34816  = 35840
#define OFF_XS   (OFF_WS + 9 * RROWS * W * 4)    // + 147456      = 183296
#define SMEM_TOTAL (OFF_XS + RROWS * W * 4)      // + 16384       = 199680

typedef unsigned long long u64;
typedef unsigned int u32;

__device__ __forceinline__ u32 s2u(const void* p) {
    u32 a;
    asm("{ .reg .u64 t; cvta.to.shared.u64 t, %1; cvt.u32.u64 %0, t; }"
        : "=r"(a) : "l"(p));
    return a;
}
__device__ __forceinline__ u64 pk(float lo, float hi) {
    u64 r; asm("mov.b64 %0, {%1,%2};" : "=l"(r) : "f"(lo), "f"(hi)); return r;
}
__device__ __forceinline__ void upk(u64 v, float& lo, float& hi) {
    asm("mov.b64 {%0,%1}, %2;" : "=f"(lo), "=f"(hi) : "l"(v));
}
__device__ __forceinline__ void fma2(u64& d, u64 a, u64 b) {
    asm("fma.rn.f32x2 %0, %1, %2, %0;" : "+l"(d) : "l"(a), "l"(b));
}
__device__ __forceinline__ u64 mul2(u64 a, u64 b) {
    u64 d; asm("mul.rn.f32x2 %0, %1, %2;" : "=l"(d) : "l"(a), "l"(b)); return d;
}
__device__ __forceinline__ float shup(float v) { return __shfl_up_sync(0xffffffffu, v, 1); }
__device__ __forceinline__ float shdn(float v) { return __shfl_down_sync(0xffffffffu, v, 1); }

__device__ __forceinline__ void mbar_wait(u32 mbar, u32 parity) {
    asm volatile(
        "{\n\t.reg .pred P;\n\t"
        "W_%=:\n\t"
        "mbarrier.try_wait.parity.shared::cta.b64 P, [%0], %1, 0x989680;\n\t"
        "@P bra.uni D_%=;\n\t"
        "bra.uni W_%=;\n\t"
        "D_%=:\n\t}"
        :: "r"(mbar), "r"(parity) : "memory");
}
__device__ __forceinline__ void bulk_g2s(u32 dst, const void* src, u32 bytes, u32 mbar) {
    asm volatile(
        "cp.async.bulk.shared::cluster.global.mbarrier::complete_tx::bytes "
        "[%0], [%1], %2, [%3];"
        :: "r"(dst), "l"(src), "r"(bytes), "r"(mbar) : "memory");
}

// Distributed prefetch: issuer k (0..8 = weight tap k, 9 = x); mbar count 10.
__device__ __forceinline__ void issue_prefetch_k(int t, int k,
                                                 const float* x, const float* wgt,
                                                 u32 ws, u32 xs, u32 mbar) {
    const int img = t >> 3;
    const int t0  = (t & 7) * TH;
    const int rlo = (t0 - 8 < 0) ? 0 : (t0 - 8);
    const int rhi = (t0 + 24 > H) ? H : (t0 + 24);
    const int nrows = rhi - rlo;
    const int droff = rlo - (t0 - 8);
    const u32 bytes = (u32)nrows * (W * 4);
    asm volatile("mbarrier.arrive.expect_tx.shared.b64 _, [%0], %1;"
                 :: "r"(mbar), "r"(bytes) : "memory");
    if (k < 9) {
        const float* src = wgt + ((size_t)(img * 9 + k) << 14) + rlo * W;
        bulk_g2s(ws + (u32)(k * RROWS + droff) * (W * 4), src, bytes, mbar);
    } else {
        bulk_g2s(xs + (u32)droff * (W * 4), x + ((size_t)img << 14) + rlo * W, bytes, mbar);
    }
}

__global__ __launch_bounds__(512, 1)
void diffusion_persist_kernel(const float* __restrict__ x,
                              const float* __restrict__ wgt,
                              float* __restrict__ out)
{
    extern __shared__ char smem[];
    float (*buf)[SROWS][W] = (float (*)[SROWS][W])(smem + OFF_BUF);
    const float* wsp = (const float*)(smem + OFF_WS);
    const float* xsp = (const float*)(smem + OFF_XS);
    const u32 mbar = s2u(smem + OFF_MBAR);
    const u32 ws_a = s2u(smem + OFF_WS);
    const u32 xs_a = s2u(smem + OFF_XS);

    const int tid  = threadIdx.x;
    const int lane = tid & 31;
    const int warp = tid >> 5;          // 0..15; owns region rows 2g, 2g+1
    const int col0 = lane << 2;
    const int g2   = warp * 2;
    // Clamped lateral columns: the clamped lanes' values hit zeroed weights.
    const int colL = (lane == 0)  ? col0     : col0 - 1;
    const int colR = (lane == 31) ? col0 + 3 : col0 + 4;
    const bool issuer = (lane == 0 && warp < 10);

    // one-time init: guard rows (region rows -1 and 32 -> zero forever), mbar
    if (tid < 128) {
        int b = tid >> 6, r = (tid >> 5) & 1;
        *(float4*)&buf[b][r ? (SROWS - 1) : 0][col0] = make_float4(0.f, 0.f, 0.f, 0.f);
    }
    if (tid == 0) {
        asm volatile("mbarrier.init.shared.b64 [%0], 10;" :: "r"(mbar) : "memory");
    }
    __syncthreads();

    int t = blockIdx.x;
    const int stride = gridDim.x;
    if (issuer && t < NT) issue_prefetch_k(t, warp, x, wgt, ws_a, xs_a, mbar);
    u32 ph = 0;

    for (; t < NT; t += stride) {
        mbar_wait(mbar, ph); ph ^= 1u;

        const int img = t >> 3;
        const int t0  = (t & 7) * TH;

        // ---- tile prologue: weights staging -> normalized packed registers
        u64 Wp[2][3][6];
        float4 y0, y1;
#pragma unroll
        for (int ro = 0; ro < 2; ro++) {
            const int rr   = g2 + ro;
            const int grow = t0 - 8 + rr;
            const bool rv  = ((unsigned)grow < (unsigned)H);
            float aa[9][4];
            if (rv) {
                float s0 = 0.f, s1 = 0.f, s2 = 0.f, s3 = 0.f;
#pragma unroll
                for (int k = 0; k < 9; k++) {
                    float4 tv = *(const float4*)&wsp[(k * RROWS + rr) * W + col0];
                    aa[k][0] = fabsf(tv.x); aa[k][1] = fabsf(tv.y);
                    aa[k][2] = fabsf(tv.z); aa[k][3] = fabsf(tv.w);
                    s0 += aa[k][0]; s1 += aa[k][1]; s2 += aa[k][2]; s3 += aa[k][3];
                }
                const float i0 = __fdividef(1.f, s0), i1 = __fdividef(1.f, s1);
                const float i2 = __fdividef(1.f, s2), i3 = __fdividef(1.f, s3);
#pragma unroll
                for (int k = 0; k < 9; k++) {
                    aa[k][0] *= i0; aa[k][1] *= i1; aa[k][2] *= i2; aa[k][3] *= i3;
                }
                if (lane == 0)  { aa[0][0] = 0.f; aa[3][0] = 0.f; aa[6][0] = 0.f; }
                if (lane == 31) { aa[2][3] = 0.f; aa[5][3] = 0.f; aa[8][3] = 0.f; }
            } else {
#pragma unroll
                for (int k = 0; k < 9; k++) {
                    aa[k][0] = 0.f; aa[k][1] = 0.f; aa[k][2] = 0.f; aa[k][3] = 0.f;
                }
            }
#pragma unroll
            for (int ki = 0; ki < 3; ki++) {
                Wp[ro][ki][0] = pk(aa[ki * 3 + 0][0], aa[ki * 3 + 0][1]);
                Wp[ro][ki][1] = pk(aa[ki * 3 + 1][0], aa[ki * 3 + 1][1]);
                Wp[ro][ki][2] = pk(aa[ki * 3 + 2][0], aa[ki * 3 + 2][1]);
                Wp[ro][ki][3] = pk(aa[ki * 3 + 0][2], aa[ki * 3 + 0][3]);
                Wp[ro][ki][4] = pk(aa[ki * 3 + 1][2], aa[ki * 3 + 1][3]);
                Wp[ro][ki][5] = pk(aa[ki * 3 + 2][2], aa[ki * 3 + 2][3]);
            }
            float4 xv = make_float4(0.f, 0.f, 0.f, 0.f);
            if (rv) xv = *(const float4*)&xsp[rr * W + col0];
            if (ro == 0) y0 = xv; else y1 = xv;
            *(float4*)&buf[0][rr + 1][col0] = xv;
        }

        // hoisted own-row operands for step 0 (register-only; pre-barrier)
        u64 p00, p01, p02, p03, p04, p10, p11, p12, p13, p14;
        {
            const float xl0 = shup(y0.w), xr0 = shdn(y0.x);
            const float xl1 = shup(y1.w), xr1 = shdn(y1.x);
            p00 = pk(xl0, y0.x); p01 = pk(y0.x, y0.y); p02 = pk(y0.y, y0.z);
            p03 = pk(y0.z, y0.w); p04 = pk(y0.w, xr0);
            p10 = pk(xl1, y1.x); p11 = pk(y1.x, y1.y); p12 = pk(y1.y, y1.z);
            p13 = pk(y1.z, y1.w); p14 = pk(y1.w, xr1);
        }
        __syncthreads();   // staging consumed + buf[0] published

        // prefetch next tile (distributed; overlaps the 8-step loop)
        if (issuer && t + stride < NT)
            issue_prefetch_k(t + stride, warp, x, wgt, ws_a, xs_a, mbar);

        // ---- 8 fused steps
#pragma unroll
        for (int s = 0; s < STEPS; s++) {
            const int cb = s & 1;
            // neighbor rows: vector + parallel lateral scalars (no shfl chain)
            const float* rowA = &buf[cb][g2][0];
            const float* rowB = &buf[cb][g2 + 3][0];
            float4 va = *(const float4*)&rowA[col0];
            const float vaL = rowA[colL], vaR = rowA[colR];
            float4 vb = *(const float4*)&rowB[col0];
            const float vbL = rowB[colL], vbR = rowB[colR];

            const u64 pA0 = pk(vaL, va.x), pA1 = pk(va.x, va.y), pA2 = pk(va.y, va.z);
            const u64 pA3 = pk(va.z, va.w), pA4 = pk(va.w, vaR);
            const u64 pB0 = pk(vbL, vb.x), pB1 = pk(vb.x, vb.y), pB2 = pk(vb.y, vb.z);
            const u64 pB3 = pk(vb.z, vb.w), pB4 = pk(vb.w, vbR);

            // chains start on own-row operands (ready at loop top)
            u64 n001 = mul2(Wp[0][1][0], p00), n023 = mul2(Wp[0][1][3], p02);
            u64 n101 = mul2(Wp[1][0][0], p00), n123 = mul2(Wp[1][0][3], p02);
            fma2(n001, Wp[0][1][1], p01); fma2(n023, Wp[0][1][4], p03);
            fma2(n101, Wp[1][0][1], p01); fma2(n123, Wp[1][0][4], p03);
            fma2(n001, Wp[0][1][2], p02); fma2(n023, Wp[0][1][5], p04);
            fma2(n101, Wp[1][0][2], p02); fma2(n123, Wp[1][0][5], p04);

            fma2(n001, Wp[0][2][0], p10); fma2(n023, Wp[0][2][3], p12);
            fma2(n101, Wp[1][1][0], p10); fma2(n123, Wp[1][1][3], p12);
            fma2(n001, Wp[0][2][1], p11); fma2(n023, Wp[0][2][4], p13);
            fma2(n101, Wp[1][1][1], p11); fma2(n123, Wp[1][1][4], p13);
            fma2(n001, Wp[0][2][2], p12); fma2(n023, Wp[0][2][5], p14);
            fma2(n101, Wp[1][1][2], p12); fma2(n123, Wp[1][1][5], p14);

            fma2(n001, Wp[0][0][0], pA0); fma2(n023, Wp[0][0][3], pA2);
            fma2(n101, Wp[1][2][0], pB0); fma2(n123, Wp[1][2][3], pB2);
            fma2(n001, Wp[0][0][1], pA1); fma2(n023, Wp[0][0][4], pA3);
            fma2(n101, Wp[1][2][1], pB1); fma2(n123, Wp[1][2][4], pB3);
            fma2(n001, Wp[0][0][2], pA2); fma2(n023, Wp[0][0][5], pA4);
            fma2(n101, Wp[1][2][2], pB2); fma2(n123, Wp[1][2][5], pB4);

            upk(n001, y0.x, y0.y); upk(n023, y0.z, y0.w);
            upk(n101, y1.x, y1.y); upk(n123, y1.z, y1.w);

            if (s < STEPS - 1) {
                // hoist next step's own-row operands (register-only) BEFORE
                // the barrier so nothing own-row remains post-barrier
                const float xl0 = shup(y0.w), xr0 = shdn(y0.x);
                const float xl1 = shup(y1.w), xr1 = shdn(y1.x);
                p00 = pk(xl0, y0.x); p01 = pk(y0.x, y0.y); p02 = pk(y0.y, y0.z);
                p03 = pk(y0.z, y0.w); p04 = pk(y0.w, xr0);
                p10 = pk(xl1, y1.x); p11 = pk(y1.x, y1.y); p12 = pk(y1.y, y1.z);
                p13 = pk(y1.z, y1.w); p14 = pk(y1.w, xr1);

                const int nb = cb ^ 1;
                *(float4*)&buf[nb][g2 + 1][col0] = y0;
                *(float4*)&buf[nb][g2 + 2][col0] = y1;
                __syncthreads();
            }
        }

        // ---- output: warps 4..11 hold the 16 exact rows (region rows 8..23)
        if ((unsigned)(warp - 4) < 8u) {
            float* ob = out + (size_t)img * IMG + (t0 + g2 - 8) * W + col0;
            *(float4*)ob       = y0;
            *(float4*)(ob + W) = y1;
        }
        // Next-tile prologue writes buf[0] only; last buf[0] reads were step 6,
        // fenced by the step-6 __syncthreads. Staging reuse fenced by mbar +
        // post-prologue __syncthreads.
    }
}

extern "C" void kernel_launch(void* const* d_in, const int* in_sizes, int n_in,
                              void* d_out, int out_size)
{
    const float* x   = (const float*)d_in[0];
    const float* wgt = (const float*)d_in[1];
    float* out       = (float*)d_out;

    int sms = 148;
    cudaDeviceGetAttribute(&sms, cudaDevAttrMultiProcessorCount, 0);
    if (sms < 1) sms = 148;
    if (sms > NT) sms = NT;

    cudaFuncSetAttribute(diffusion_persist_kernel,
                         cudaFuncAttributeMaxDynamicSharedMemorySize, SMEM_TOTAL);
    diffusion_persist_kernel<<<sms, 512, SMEM_TOTAL>>>(x, wgt, out);
}